// round 1
// baseline (speedup 1.0000x reference)
#include <cuda_runtime.h>

#define BB 16
#define NN 8192
#define SS 1024
#define GG 32
#define CC 64
#define OC 128

// ---------------- scratch (device globals; no runtime allocation) ----------------
__device__ float4 g_pts[BB * NN];                      // xyz + |p|^2
__device__ int    g_fps[BB * SS];                      // fps indices
__device__ int    g_gidx[BB * SS * GG];                // final group indices (radius-replaced)
__device__ float  g_F[(size_t)BB * NN * OC];           // per-point feature @ W (64 MB)

// ---------------- K0: pack coords as float4 with squared norm ----------------
__global__ void k_prep(const float* __restrict__ coor) {
    int p = blockIdx.x * 256 + threadIdx.x;
    int b = blockIdx.y;
    if (p < NN) {
        float x = coor[((size_t)b * 3 + 0) * NN + p];
        float y = coor[((size_t)b * 3 + 1) * NN + p];
        float z = coor[((size_t)b * 3 + 2) * NN + p];
        g_pts[b * NN + p] = make_float4(x, y, z, x * x + y * y + z * z);
    }
}

// ---------------- K1: farthest point sampling (1 block per batch) ----------------
__global__ __launch_bounds__(1024) void k_fps(float* __restrict__ outc) {
    __shared__ float s_cx, s_cy, s_cz;
    __shared__ int   s_f;
    __shared__ unsigned long long s_red[32];
    int b = blockIdx.x, tid = threadIdx.x;
    const float4* pts = &g_pts[b * NN];

    float px[8], py[8], pz[8], dist[8];
#pragma unroll
    for (int k = 0; k < 8; k++) {
        float4 p = pts[tid + (k << 10)];
        px[k] = p.x; py[k] = p.y; pz[k] = p.z; dist[k] = 1e10f;
    }
    if (tid == 0) {
        float4 c = pts[0];
        s_cx = c.x; s_cy = c.y; s_cz = c.z; s_f = 0;
    }
    __syncthreads();
    int wid = tid >> 5, lane = tid & 31;

    for (int s = 0; s < SS; s++) {
        float cx = s_cx, cy = s_cy, cz = s_cz;
        if (tid == 0) {
            g_fps[b * SS + s] = s_f;
            outc[((size_t)b * 3 + 0) * SS + s] = cx;
            outc[((size_t)b * 3 + 1) * SS + s] = cy;
            outc[((size_t)b * 3 + 2) * SS + s] = cz;
        }
        float bm = -1.f; int bi = 0;
#pragma unroll
        for (int k = 0; k < 8; k++) {
            // match reference rounding: separate mul/adds, no FMA contraction
            float dx = __fadd_rn(px[k], -cx);
            float dy = __fadd_rn(py[k], -cy);
            float dz = __fadd_rn(pz[k], -cz);
            float d  = __fadd_rn(__fadd_rn(__fmul_rn(dx, dx), __fmul_rn(dy, dy)),
                                 __fmul_rn(dz, dz));
            float nd = fminf(dist[k], d);
            dist[k] = nd;
            if (nd > bm) { bm = nd; bi = tid + (k << 10); }  // strict > keeps lowest k
        }
        // warp argmax, first-index tie-break
#pragma unroll
        for (int off = 16; off; off >>= 1) {
            float ov = __shfl_down_sync(0xffffffffu, bm, off);
            int   oi = __shfl_down_sync(0xffffffffu, bi, off);
            if (ov > bm || (ov == bm && oi < bi)) { bm = ov; bi = oi; }
        }
        if (lane == 0)
            s_red[wid] = ((unsigned long long)__float_as_uint(bm) << 32) |
                         (unsigned)(NN - 1 - bi);  // larger (N-1-i) <=> smaller i on ties
        __syncthreads();
        if (wid == 0) {
            unsigned long long v = s_red[lane];
#pragma unroll
            for (int off = 16; off; off >>= 1) {
                unsigned long long o = __shfl_down_sync(0xffffffffu, v, off);
                if (o > v) v = o;
            }
            if (lane == 0) {
                int nf = (NN - 1) - (int)(v & 0xffffffffu);
                float4 c = pts[nf];   // L1-resident (128 KB working set)
                s_cx = c.x; s_cy = c.y; s_cz = c.z; s_f = nf;
            }
        }
        __syncthreads();
    }
}

// ---------------- K2: hybrid KNN/ball query (1 warp per query) ----------------
__global__ __launch_bounds__(512) void k_group() {
    int b    = blockIdx.y;
    int warp = threadIdx.x >> 5, lane = threadIdx.x & 31;
    int s    = blockIdx.x * 16 + warp;
    const float4* pts = &g_pts[b * NN];

    int fidx = g_fps[b * SS + s];
    float4 c = pts[fidx];
    float cx = c.x, cy = c.y, cz = c.z, cw = c.w;

    // key: sortable(dist) in hi 32, idx in lo 32 -> smaller key == closer / lower idx
    unsigned long long kept;
    {
        float4 p = pts[lane];
        float dot = fmaf(cx, p.x, fmaf(cy, p.y, cz * p.z));
        float d = fmaf(-2.f, dot, cw + p.w);
        unsigned bits = __float_as_uint(d);
        unsigned u = bits ^ (unsigned)(((int)bits >> 31) | (int)0x80000000);
        kept = ((unsigned long long)u << 32) | (unsigned)lane;
    }
    unsigned long long tv = kept; int tl = lane;
#pragma unroll
    for (int m = 1; m < 32; m <<= 1) {
        unsigned long long ov = __shfl_xor_sync(0xffffffffu, tv, m);
        int ol = __shfl_xor_sync(0xffffffffu, tl, m);
        if (ov > tv) { tv = ov; tl = ol; }
    }
    unsigned long long thr = tv; int maxLane = tl;

    for (int base = 32; base < NN; base += 32) {
        float4 p = pts[base + lane];
        float dot = fmaf(cx, p.x, fmaf(cy, p.y, cz * p.z));
        float d = fmaf(-2.f, dot, cw + p.w);
        unsigned bits = __float_as_uint(d);
        unsigned u = bits ^ (unsigned)(((int)bits >> 31) | (int)0x80000000);
        unsigned long long k = ((unsigned long long)u << 32) | (unsigned)(base + lane);

        unsigned mask = __ballot_sync(0xffffffffu, k < thr);
        while (mask) {
            int src = __ffs(mask) - 1; mask &= mask - 1;
            unsigned long long kk = __shfl_sync(0xffffffffu, k, src);
            if (kk < thr) {
                if (lane == maxLane) kept = kk;       // replace current worst
                unsigned long long v2 = kept; int l2 = lane;
#pragma unroll
                for (int m = 1; m < 32; m <<= 1) {
                    unsigned long long ov = __shfl_xor_sync(0xffffffffu, v2, m);
                    int ol = __shfl_xor_sync(0xffffffffu, l2, m);
                    if (ov > v2) { v2 = ov; l2 = ol; }
                }
                thr = v2; maxLane = l2;
            }
        }
    }
    // nearest point (min key)
    unsigned long long mn = kept;
#pragma unroll
    for (int m = 1; m < 32; m <<= 1) {
        unsigned long long ov = __shfl_xor_sync(0xffffffffu, mn, m);
        if (ov < mn) mn = ov;
    }
    int nidx = (int)(mn & 0xffffffffu);
    unsigned u = (unsigned)(kept >> 32);
    unsigned bits = (u & 0x80000000u) ? (u ^ 0x80000000u) : ~u;
    float d = __uint_as_float(bits);
    int myidx = (int)(kept & 0xffffffffu);
    int outi = (d > 1.0f) ? nidx : myidx;   // ball-query replacement (RADIUS^2 = 1)
    g_gidx[(b * SS + s) * GG + lane] = outi;
}

// ---------------- K3: dense per-point feature GEMM  F = fea^T @ Wf^T ----------------
// F[b][p][o] = sum_c fea[b][c][p] * W[o][c]   (c < 64)
__global__ __launch_bounds__(256) void k_fgemm(const float* __restrict__ fea,
                                               const float* __restrict__ W) {
    __shared__ float As[32][128];   // [k][p]
    __shared__ float Bs[32][64];    // [k][o]
    int b  = blockIdx.z;
    int p0 = blockIdx.x * 128;
    int o0 = blockIdx.y * 64;
    int tx = threadIdx.x & 15;      // o tile (4 each)
    int ty = threadIdx.x >> 4;      // p tile (8 each)

    float acc[8][4];
#pragma unroll
    for (int i = 0; i < 8; i++)
#pragma unroll
        for (int j = 0; j < 4; j++) acc[i][j] = 0.f;

    for (int kk = 0; kk < CC; kk += 32) {
        __syncthreads();
        for (int i = threadIdx.x; i < 32 * 128; i += 256) {
            int cidx = i >> 7, p = i & 127;
            As[cidx][p] = fea[((size_t)(b * CC + kk + cidx)) * NN + p0 + p];
        }
        for (int i = threadIdx.x; i < 32 * 64; i += 256) {
            int cidx = i >> 6, o = i & 63;
            Bs[cidx][o] = W[(o0 + o) * 67 + kk + cidx];
        }
        __syncthreads();
#pragma unroll
        for (int k = 0; k < 32; k++) {
            float af[8], bf[4];
#pragma unroll
            for (int i = 0; i < 8; i++) af[i] = As[k][ty * 8 + i];
#pragma unroll
            for (int j = 0; j < 4; j++) bf[j] = Bs[k][tx * 4 + j];
#pragma unroll
            for (int i = 0; i < 8; i++)
#pragma unroll
                for (int j = 0; j < 4; j++)
                    acc[i][j] = fmaf(af[i], bf[j], acc[i][j]);
        }
    }
#pragma unroll
    for (int i = 0; i < 8; i++) {
        int p = p0 + ty * 8 + i;
        float4 v = make_float4(acc[i][0], acc[i][1], acc[i][2], acc[i][3]);
        *(float4*)&g_F[((size_t)(b * NN + p)) * OC + o0 + tx * 4] = v;
    }
}

// ---------------- K4: gather + coord term + ReLU + group max ----------------
__global__ __launch_bounds__(128) void k_final(const float* __restrict__ W,
                                               const float* __restrict__ outc,
                                               float* __restrict__ outf) {
    __shared__ int   s_idx[GG];
    __shared__ float s_rc[3][GG];
    int b = blockIdx.y, s = blockIdx.x;
    int tid = threadIdx.x;
    if (tid < GG) {
        int i = g_gidx[(b * SS + s) * GG + tid];
        s_idx[tid] = i;
        float4 p = g_pts[b * NN + i];
        s_rc[0][tid] = p.x - outc[((size_t)b * 3 + 0) * SS + s];
        s_rc[1][tid] = p.y - outc[((size_t)b * 3 + 1) * SS + s];
        s_rc[2][tid] = p.z - outc[((size_t)b * 3 + 2) * SS + s];
    }
    __syncthreads();
    int o = tid;
    float w0 = W[o * 67 + 64], w1 = W[o * 67 + 65], w2 = W[o * 67 + 66];
    float m = 0.f;   // relu(v) >= 0, so max with init 0 == max(relu(v))
#pragma unroll 8
    for (int g = 0; g < GG; g++) {
        float v = g_F[((size_t)(b * NN + s_idx[g])) * OC + o];
        v = fmaf(s_rc[0][g], w0, v);
        v = fmaf(s_rc[1][g], w1, v);
        v = fmaf(s_rc[2][g], w2, v);
        m = fmaxf(m, v);
    }
    outf[((size_t)(b * OC + o)) * SS + s] = m;
}

// ---------------- launch ----------------
extern "C" void kernel_launch(void* const* d_in, const int* in_sizes, int n_in,
                              void* d_out, int out_size) {
    const float* coor = (const float*)d_in[0];
    const float* fea  = (const float*)d_in[1];
    const float* W    = (const float*)d_in[2];
    float* outc = (float*)d_out;                 // (B,3,S)
    float* outf = outc + (size_t)BB * 3 * SS;    // (B,2C,S)

    k_prep <<<dim3(32, BB), 256>>>(coor);
    k_fps  <<<BB, 1024>>>(outc);
    k_fgemm<<<dim3(64, 2, BB), 256>>>(fea, W);
    k_group<<<dim3(64, BB), 512>>>();
    k_final<<<dim3(SS, BB), 128>>>(W, outc, outf);
}

// round 2
// speedup vs baseline: 1.7309x; 1.7309x over previous
#include <cuda_runtime.h>

#define BB 16
#define NN 8192
#define SS 1024
#define GG 32
#define CC 64
#define OC 128

// ---------------- scratch (device globals; no runtime allocation) ----------------
__device__ float4 g_pts[BB * NN];                      // xyz + |p|^2
__device__ int    g_fps[BB * SS];                      // fps indices
__device__ int    g_gidx[BB * SS * GG];                // group indices (radius-replaced)
__device__ float  g_F[(size_t)BB * NN * OC];           // per-point feature @ W (64 MB)

// ---------------- packed f32x2 helpers (bit-identical .rn rounding) ----------------
__device__ __forceinline__ unsigned long long f2pack(float a, float b) {
    unsigned long long r;
    asm("mov.b64 %0, {%1, %2};" : "=l"(r) : "f"(a), "f"(b));
    return r;
}
__device__ __forceinline__ void f2unpack(unsigned long long v, float& a, float& b) {
    asm("mov.b64 {%0, %1}, %2;" : "=f"(a), "=f"(b) : "l"(v));
}
__device__ __forceinline__ unsigned long long fadd2(unsigned long long a, unsigned long long b) {
    unsigned long long r;
    asm("add.rn.f32x2 %0, %1, %2;" : "=l"(r) : "l"(a), "l"(b));
    return r;
}
__device__ __forceinline__ unsigned long long fmul2(unsigned long long a, unsigned long long b) {
    unsigned long long r;
    asm("mul.rn.f32x2 %0, %1, %2;" : "=l"(r) : "l"(a), "l"(b));
    return r;
}

// ---------------- K0: pack coords as float4 with squared norm ----------------
__global__ void k_prep(const float* __restrict__ coor) {
    int p = blockIdx.x * 256 + threadIdx.x;
    int b = blockIdx.y;
    if (p < NN) {
        float x = coor[((size_t)b * 3 + 0) * NN + p];
        float y = coor[((size_t)b * 3 + 1) * NN + p];
        float z = coor[((size_t)b * 3 + 2) * NN + p];
        g_pts[b * NN + p] = make_float4(x, y, z, x * x + y * y + z * z);
    }
}

// ---------------- K1: farthest point sampling (1 block per batch) ----------------
// Packed f32x2 distance math, REDUX-based two-stage argmax, one barrier/step.
__global__ __launch_bounds__(1024) void k_fps(float* __restrict__ outc) {
    __shared__ unsigned long long s_red[2][32];
    int b = blockIdx.x, tid = threadIdx.x, lane = tid & 31, wid = tid >> 5;
    const float4* pts = &g_pts[b * NN];

    unsigned long long px2[4], py2[4], pz2[4];
    float dist[8];
#pragma unroll
    for (int k = 0; k < 4; k++) {
        float4 a = pts[tid + ((2 * k) << 10)];
        float4 c = pts[tid + ((2 * k + 1) << 10)];
        px2[k] = f2pack(a.x, c.x);
        py2[k] = f2pack(a.y, c.y);
        pz2[k] = f2pack(a.z, c.z);
        dist[2 * k] = 1e10f; dist[2 * k + 1] = 1e10f;
    }
    float4 c0 = pts[0];
    float cx = c0.x, cy = c0.y, cz = c0.z;
    int cur = 0;

    for (int s = 0; s < SS; s++) {
        if (tid == 0) {
            g_fps[b * SS + s] = cur;
            outc[((size_t)b * 3 + 0) * SS + s] = cx;
            outc[((size_t)b * 3 + 1) * SS + s] = cy;
            outc[((size_t)b * 3 + 2) * SS + s] = cz;
        }
        unsigned long long ncx2 = f2pack(-cx, -cx);
        unsigned long long ncy2 = f2pack(-cy, -cy);
        unsigned long long ncz2 = f2pack(-cz, -cz);
        float bm = -1.0f;
#pragma unroll
        for (int k = 0; k < 4; k++) {
            // (p - c) as p + (-c); d = ((dx*dx + dy*dy) + dz*dz)  — same rounding
            // as the reference-matching scalar version, two points per instr.
            unsigned long long dx2 = fadd2(px2[k], ncx2);
            unsigned long long dy2 = fadd2(py2[k], ncy2);
            unsigned long long dz2 = fadd2(pz2[k], ncz2);
            unsigned long long sq = fadd2(fadd2(fmul2(dx2, dx2), fmul2(dy2, dy2)),
                                          fmul2(dz2, dz2));
            float d0, d1;
            f2unpack(sq, d0, d1);
            dist[2 * k]     = fminf(dist[2 * k], d0);
            dist[2 * k + 1] = fminf(dist[2 * k + 1], d1);
            bm = fmaxf(bm, dist[2 * k]);
            bm = fmaxf(bm, dist[2 * k + 1]);
        }
        // recover lowest slot equal to the max (lowest index tie-break)
        int bk = 7;
#pragma unroll
        for (int k = 6; k >= 0; k--) bk = (dist[k] == bm) ? k : bk;

        // warp argmax: dist >= 0 so float bits are uint-monotonic
        unsigned vb = __float_as_uint(bm);
        unsigned m  = __reduce_max_sync(0xffffffffu, vb);
        unsigned rk = (vb == m) ? (unsigned)(NN - 1 - (tid + (bk << 10))) : 0u;
        unsigned m2 = __reduce_max_sync(0xffffffffu, rk);   // max(N-1-i) == min i
        if (lane == 0)
            s_red[s & 1][wid] = ((unsigned long long)m << 32) | m2;
        __syncthreads();
        // stage 2: every warp reduces the 32 warp-candidates (no second barrier;
        // double-buffered s_red makes the next step's writes race-free)
        unsigned long long v = s_red[s & 1][lane];
        unsigned hi = (unsigned)(v >> 32);
        unsigned M  = __reduce_max_sync(0xffffffffu, hi);
        unsigned lo = (hi == M) ? (unsigned)v : 0u;
        unsigned M2 = __reduce_max_sync(0xffffffffu, lo);
        int nf = NN - 1 - (int)M2;
        float4 cc = pts[nf];   // warp-uniform: single L1 broadcast
        cx = cc.x; cy = cc.y; cz = cc.z; cur = nf;
    }
}

// ---------------- K2: hybrid KNN/ball query (1 warp per query) ----------------
__global__ __launch_bounds__(512) void k_group() {
    int b    = blockIdx.y;
    int warp = threadIdx.x >> 5, lane = threadIdx.x & 31;
    int s    = blockIdx.x * 16 + warp;
    const float4* pts = &g_pts[b * NN];

    float4 c = pts[g_fps[b * SS + s]];
    float cx = c.x, cy = c.y, cz = c.z, cw = c.w;

    // first 32 candidates
    float4 p = pts[lane];
    float dot = fmaf(cx, p.x, fmaf(cy, p.y, cz * p.z));
    float d   = fmaf(-2.f, dot, cw + p.w);
    unsigned bits = __float_as_uint(d);
    unsigned u = bits ^ (unsigned)(((int)bits >> 31) | (int)0x80000000);
    unsigned long long kept = ((unsigned long long)u << 32) | (unsigned)lane;

    unsigned thr_hi; unsigned long long thr_key; int maxLane;
    {
        unsigned hi = (unsigned)(kept >> 32);
        unsigned M  = __reduce_max_sync(0xffffffffu, hi);
        unsigned lo = (hi == M) ? (unsigned)kept : 0u;
        unsigned M2 = __reduce_max_sync(0xffffffffu, lo);
        thr_hi = M; thr_key = ((unsigned long long)M << 32) | M2;
        maxLane = __ffs(__ballot_sync(0xffffffffu, kept == thr_key)) - 1;
    }

    for (int base = 32; base < NN; base += 32) {
        float4 q = pts[base + lane];
        float dq = fmaf(cx, q.x, fmaf(cy, q.y, cz * q.z));
        float dd = fmaf(-2.f, dq, cw + q.w);
        unsigned b2 = __float_as_uint(dd);
        unsigned uu = b2 ^ (unsigned)(((int)b2 >> 31) | (int)0x80000000);
        // strict <: an equal-distance later-index candidate can never enter
        // (kept entries always have earlier indices), so u32 compare is exact.
        unsigned mask = __ballot_sync(0xffffffffu, uu < thr_hi);
        if (mask) {
            unsigned long long key =
                ((unsigned long long)uu << 32) | (unsigned)(base + lane);
            do {
                int src = __ffs(mask) - 1; mask &= mask - 1;
                unsigned long long kk = __shfl_sync(0xffffffffu, key, src);
                if (kk < thr_key) {
                    if (lane == maxLane) kept = kk;   // replace current worst
                    unsigned hi = (unsigned)(kept >> 32);
                    unsigned M  = __reduce_max_sync(0xffffffffu, hi);
                    unsigned lo = (hi == M) ? (unsigned)kept : 0u;
                    unsigned M2 = __reduce_max_sync(0xffffffffu, lo);
                    thr_hi = M; thr_key = ((unsigned long long)M << 32) | M2;
                    maxLane = __ffs(__ballot_sync(0xffffffffu, kept == thr_key)) - 1;
                }
            } while (mask);
        }
    }
    // nearest (min key) for ball-query replacement
    unsigned hi = (unsigned)(kept >> 32);
    unsigned Mn  = __reduce_min_sync(0xffffffffu, hi);
    unsigned lon = (hi == Mn) ? (unsigned)kept : 0xffffffffu;
    unsigned M2n = __reduce_min_sync(0xffffffffu, lon);
    int nidx  = (int)M2n;
    int myidx = (int)(unsigned)kept;
    // d > 1.0f  <=>  sortable(d) > sortable(1.0f) = 0xBF800000 (strict, exact)
    int outi = (hi > 0xBF800000u) ? nidx : myidx;
    g_gidx[(b * SS + s) * GG + lane] = outi;
}

// ---------------- K3: dense per-point feature GEMM  F[b][p][o] = fea·Wf ----------------
__global__ __launch_bounds__(256) void k_fgemm(const float* __restrict__ fea,
                                               const float* __restrict__ W) {
    __shared__ float As[32][128];   // [k][p]
    __shared__ float Bs[32][64];    // [k][o]
    int b  = blockIdx.z;
    int p0 = blockIdx.x * 128;
    int o0 = blockIdx.y * 64;
    int tx = threadIdx.x & 15;      // o tile (4 each)
    int ty = threadIdx.x >> 4;      // p tile (8 each)

    float acc[8][4];
#pragma unroll
    for (int i = 0; i < 8; i++)
#pragma unroll
        for (int j = 0; j < 4; j++) acc[i][j] = 0.f;

    for (int kk = 0; kk < CC; kk += 32) {
        __syncthreads();
        for (int i = threadIdx.x; i < 32 * 128; i += 256) {
            int cidx = i >> 7, p = i & 127;
            As[cidx][p] = fea[((size_t)(b * CC + kk + cidx)) * NN + p0 + p];
        }
        for (int i = threadIdx.x; i < 32 * 64; i += 256) {
            int cidx = i >> 6, o = i & 63;
            Bs[cidx][o] = W[(o0 + o) * 67 + kk + cidx];
        }
        __syncthreads();
#pragma unroll
        for (int k = 0; k < 32; k++) {
            float af[8], bf[4];
#pragma unroll
            for (int i = 0; i < 8; i++) af[i] = As[k][ty * 8 + i];
#pragma unroll
            for (int j = 0; j < 4; j++) bf[j] = Bs[k][tx * 4 + j];
#pragma unroll
            for (int i = 0; i < 8; i++)
#pragma unroll
                for (int j = 0; j < 4; j++)
                    acc[i][j] = fmaf(af[i], bf[j], acc[i][j]);
        }
    }
#pragma unroll
    for (int i = 0; i < 8; i++) {
        int p = p0 + ty * 8 + i;
        float4 v = make_float4(acc[i][0], acc[i][1], acc[i][2], acc[i][3]);
        *(float4*)&g_F[((size_t)(b * NN + p)) * OC + o0 + tx * 4] = v;
    }
}

// ---------------- K4: gather + coord term + ReLU + group max ----------------
__global__ __launch_bounds__(128) void k_final(const float* __restrict__ W,
                                               const float* __restrict__ outc,
                                               float* __restrict__ outf) {
    __shared__ int   s_idx[GG];
    __shared__ float s_rc[3][GG];
    int b = blockIdx.y, s = blockIdx.x;
    int tid = threadIdx.x;
    if (tid < GG) {
        int i = g_gidx[(b * SS + s) * GG + tid];
        s_idx[tid] = i;
        float4 p = g_pts[b * NN + i];
        s_rc[0][tid] = p.x - outc[((size_t)b * 3 + 0) * SS + s];
        s_rc[1][tid] = p.y - outc[((size_t)b * 3 + 1) * SS + s];
        s_rc[2][tid] = p.z - outc[((size_t)b * 3 + 2) * SS + s];
    }
    __syncthreads();
    int o = tid;
    float w0 = W[o * 67 + 64], w1 = W[o * 67 + 65], w2 = W[o * 67 + 66];
    float m = 0.f;   // relu(v) >= 0, so max with init 0 == max(relu(v))
#pragma unroll 8
    for (int g = 0; g < GG; g++) {
        float v = g_F[((size_t)(b * NN + s_idx[g])) * OC + o];
        v = fmaf(s_rc[0][g], w0, v);
        v = fmaf(s_rc[1][g], w1, v);
        v = fmaf(s_rc[2][g], w2, v);
        m = fmaxf(m, v);
    }
    outf[((size_t)(b * OC + o)) * SS + s] = m;
}

// ---------------- launch: fork k_fgemm onto a side stream to overlap with FPS ----------------
extern "C" void kernel_launch(void* const* d_in, const int* in_sizes, int n_in,
                              void* d_out, int out_size) {
    const float* coor = (const float*)d_in[0];
    const float* fea  = (const float*)d_in[1];
    const float* W    = (const float*)d_in[2];
    float* outc = (float*)d_out;                 // (B,3,S)
    float* outf = outc + (size_t)BB * 3 * SS;    // (B,2C,S)

    static cudaStream_t s2 = nullptr;
    static cudaEvent_t evA = nullptr, evB = nullptr;
    if (s2 == nullptr) {
        cudaStreamCreateWithFlags(&s2, cudaStreamNonBlocking);
        cudaEventCreateWithFlags(&evA, cudaEventDisableTiming);
        cudaEventCreateWithFlags(&evB, cudaEventDisableTiming);
    }

    // fork: GEMM is independent of FPS/grouping — run it on the idle SMs
    cudaEventRecord(evA, 0);
    cudaStreamWaitEvent(s2, evA, 0);
    k_fgemm<<<dim3(64, 2, BB), 256, 0, s2>>>(fea, W);
    cudaEventRecord(evB, s2);

    k_prep <<<dim3(32, BB), 256>>>(coor);
    k_fps  <<<BB, 1024>>>(outc);
    k_group<<<dim3(64, BB), 512>>>();

    // join before the final fused gather/conv/max
    cudaStreamWaitEvent(0, evB, 0);
    k_final<<<dim3(SS, BB), 128>>>(W, outc, outf);
}